// round 8
// baseline (speedup 1.0000x reference)
#include <cuda_runtime.h>

// DelayBuffer: out[b, t, i*D + c] = emb[b, t - d_i, c] if t >= d_i else emb[b, t, c]
// d_i in (1, 2, 4, 8, 16, 32) = 1 << i
// B=4, S=4096, D=1024 (fp32). Output [B, S, 6*D].
//
// One block (256 threads) handles one (b, t): all 6 delay segments.
// Each thread issues 6 independent float4 loads (MLP=6, hides DRAM/L2
// latency), then 6 streaming float4 stores into the contiguous 24 KiB
// output row. Input (64 MiB) stays L2-resident; output (402 MiB) streams
// through with evict-first stores.

static constexpr int B  = 4;
static constexpr int S  = 4096;
static constexpr int D  = 1024;
static constexpr int D4 = D / 4;   // 256 float4 per segment
static constexpr int ND = 6;       // number of delays

__global__ __launch_bounds__(D4, 8)
void delay_buffer_kernel(const float4* __restrict__ in, float4* __restrict__ out) {
    const int c4 = threadIdx.x;    // 0..255 within a segment
    const int t  = blockIdx.x;     // 0..4095
    const int b  = blockIdx.y;     // 0..3

    const int row = b * S + t;

    // 6 independent loads, batched for MLP
    float4 v[ND];
#pragma unroll
    for (int i = 0; i < ND; i++) {
        const int d = 1 << i;                       // DELAYS = (1,2,4,8,16,32)
        const int src_t = (t >= d) ? (t - d) : t;
        v[i] = __ldg(&in[(b * S + src_t) * D4 + c4]);
    }

    // 6 streaming stores into contiguous output row [row, 6*D]
    float4* orow = out + (size_t)row * (ND * D4) + c4;
#pragma unroll
    for (int i = 0; i < ND; i++) {
        __stcs(orow + i * D4, v[i]);
    }
}

extern "C" void kernel_launch(void* const* d_in, const int* in_sizes, int n_in,
                              void* d_out, int out_size) {
    const float4* in = (const float4*)d_in[0];
    float4* out = (float4*)d_out;

    dim3 grid(S, B);
    delay_buffer_kernel<<<grid, D4>>>(in, out);
}

// round 9
// speedup vs baseline: 1.0031x; 1.0031x over previous
#include <cuda_runtime.h>

// DelayBuffer: out[b, t, i*D + c] = emb[b, t - d_i, c] if t >= d_i else emb[b, t, c]
// d_i in (1, 2, 4, 8, 16, 32) = 1 << i
// B=4, S=4096, D=1024 (fp32). Output [B, S, 6*D].
//
// One block (256 threads) handles one (b, t): all 6 delay segments.
// Each thread issues 6 independent float4 loads (MLP=6, hides DRAM/L2
// latency), then 6 streaming float4 stores into the contiguous 24 KiB
// output row. Input (64 MiB) stays L2-resident; output (402 MiB) streams
// through with evict-first stores.

static constexpr int B  = 4;
static constexpr int S  = 4096;
static constexpr int D  = 1024;
static constexpr int D4 = D / 4;   // 256 float4 per segment
static constexpr int ND = 6;       // number of delays

__global__ __launch_bounds__(D4, 8)
void delay_buffer_kernel(const float4* __restrict__ in, float4* __restrict__ out) {
    const int c4 = threadIdx.x;    // 0..255 within a segment
    const int t  = blockIdx.x;     // 0..4095
    const int b  = blockIdx.y;     // 0..3

    const int row = b * S + t;

    // 6 independent loads, batched for MLP
    float4 v[ND];
#pragma unroll
    for (int i = 0; i < ND; i++) {
        const int d = 1 << i;                       // DELAYS = (1,2,4,8,16,32)
        const int src_t = (t >= d) ? (t - d) : t;
        v[i] = __ldg(&in[(b * S + src_t) * D4 + c4]);
    }

    // 6 streaming stores into contiguous output row [row, 6*D]
    float4* orow = out + (size_t)row * (ND * D4) + c4;
#pragma unroll
    for (int i = 0; i < ND; i++) {
        __stcs(orow + i * D4, v[i]);
    }
}

extern "C" void kernel_launch(void* const* d_in, const int* in_sizes, int n_in,
                              void* d_out, int out_size) {
    const float4* in = (const float4*)d_in[0];
    float4* out = (float4*)d_out;

    dim3 grid(S, B);
    delay_buffer_kernel<<<grid, D4>>>(in, out);
}